// round 1
// baseline (speedup 1.0000x reference)
#include <cuda_runtime.h>
#include <math_constants.h>

#define N_TOK   16384
#define IN_FEAT 4096
#define N_EXP   64
#define CAPACITY 640

#define BM 128
#define BK 32

// persistent scratch (no allocations allowed)
__device__ float          g_logits[(size_t)N_TOK * N_EXP];
__device__ int            g_counts[N_EXP];
__device__ int            g_elist[(size_t)N_EXP * N_TOK];   // encoded token*2+slot per expert
__device__ int            g_topidx[N_TOK * 2];
__device__ float          g_topp[N_TOK * 2];
__device__ unsigned char  g_drop[N_TOK * 2];

// ---------------------------------------------------------------------------
// init: zero counts + drop flags (must be re-done every launch)
// ---------------------------------------------------------------------------
__global__ void init_kernel() {
    int i = blockIdx.x * blockDim.x + threadIdx.x;
    if (i < N_EXP) g_counts[i] = 0;
    if (i < 2 * N_TOK) g_drop[i] = 0;
}

// ---------------------------------------------------------------------------
// GEMM: logits[m,e] = sum_k X[m,k] * W[e,k]   (fp32, packed f32x2 FMA)
// tile: BM=128 tokens x 64 experts x BK=32, 256 threads,
// each thread: 8 tokens (4 f32x2 pairs) x 4 experts
// ---------------------------------------------------------------------------
__global__ __launch_bounds__(256, 1) void gemm_kernel(const float* __restrict__ X,
                                                      const float* __restrict__ W) {
    __shared__ float As[BK][BM];      // transposed x tile, 16 KB
    __shared__ float Bs[BK][N_EXP];   // transposed W tile,  8 KB

    const int tid    = threadIdx.x;
    const int m_base = blockIdx.x * BM;
    const int ty = tid >> 4;          // 0..15
    const int tx = tid & 15;          // 0..15
    const int m0 = ty * 8;            // token sub-tile start (pairs of 2)
    const int e0 = tx * 4;            // expert sub-tile start

    unsigned long long acc[4][4];
    #pragma unroll
    for (int i = 0; i < 4; i++)
        #pragma unroll
        for (int j = 0; j < 4; j++) acc[i][j] = 0ULL;   // (0.0f, 0.0f)

    for (int k0 = 0; k0 < IN_FEAT; k0 += BK) {
        // --- load X tile [128, 32] as float4, store transposed ---
        #pragma unroll
        for (int r = 0; r < 4; r++) {
            int idx = tid + r * 256;           // 0..1023
            int m   = idx >> 3;
            int k4  = idx & 7;
            float4 v = *(const float4*)(X + (size_t)(m_base + m) * IN_FEAT + k0 + k4 * 4);
            As[k4 * 4 + 0][m] = v.x;
            As[k4 * 4 + 1][m] = v.y;
            As[k4 * 4 + 2][m] = v.z;
            As[k4 * 4 + 3][m] = v.w;
        }
        // --- load W tile [64, 32] ---
        #pragma unroll
        for (int r = 0; r < 2; r++) {
            int idx = tid + r * 256;           // 0..511
            int e   = idx >> 3;
            int k4  = idx & 7;
            float4 v = *(const float4*)(W + (size_t)e * IN_FEAT + k0 + k4 * 4);
            Bs[k4 * 4 + 0][e] = v.x;
            Bs[k4 * 4 + 1][e] = v.y;
            Bs[k4 * 4 + 2][e] = v.z;
            Bs[k4 * 4 + 3][e] = v.w;
        }
        __syncthreads();

        #pragma unroll
        for (int kk = 0; kk < BK; kk++) {
            unsigned long long a[4];
            #pragma unroll
            for (int i = 0; i < 4; i++)
                a[i] = *(const unsigned long long*)(&As[kk][m0 + 2 * i]);
            unsigned long long b[4];
            #pragma unroll
            for (int j = 0; j < 4; j++) {
                unsigned int bw = __float_as_uint(Bs[kk][e0 + j]);
                asm("mov.b64 %0, {%1, %1};" : "=l"(b[j]) : "r"(bw));
            }
            #pragma unroll
            for (int i = 0; i < 4; i++)
                #pragma unroll
                for (int j = 0; j < 4; j++)
                    asm("fma.rn.f32x2 %0, %1, %2, %0;"
                        : "+l"(acc[i][j]) : "l"(a[i]), "l"(b[j]));
        }
        __syncthreads();
    }

    // --- epilogue: unpack pairs, write logits ---
    #pragma unroll
    for (int i = 0; i < 4; i++) {
        int m = m_base + m0 + 2 * i;
        #pragma unroll
        for (int j = 0; j < 4; j++) {
            unsigned int lo = (unsigned int)(acc[i][j] & 0xFFFFFFFFULL);
            unsigned int hi = (unsigned int)(acc[i][j] >> 32);
            g_logits[(size_t)m * N_EXP + e0 + j]       = __uint_as_float(lo);
            g_logits[(size_t)(m + 1) * N_EXP + e0 + j] = __uint_as_float(hi);
        }
    }
}

// ---------------------------------------------------------------------------
// top-2 + softmax + histogram + per-expert list append. One warp per token.
// Tie-break matches jax.lax.top_k: equal value -> lower index first.
// ---------------------------------------------------------------------------
__global__ void topk_kernel() {
    int gwarp = (blockIdx.x * blockDim.x + threadIdx.x) >> 5;
    int lane  = threadIdx.x & 31;
    if (gwarp >= N_TOK) return;

    const float* row = g_logits + (size_t)gwarp * N_EXP;
    float v0 = row[lane];
    float v1 = row[lane + 32];

    // per-lane best (tie -> lower index = v0's index)
    float bv; int bi;
    if (v1 > v0) { bv = v1; bi = lane + 32; } else { bv = v0; bi = lane; }

    float mv = bv; int mi = bi;
    #pragma unroll
    for (int off = 16; off; off >>= 1) {
        float ov = __shfl_xor_sync(0xFFFFFFFFu, mv, off);
        int   oi = __shfl_xor_sync(0xFFFFFFFFu, mi, off);
        if (ov > mv || (ov == mv && oi < mi)) { mv = ov; mi = oi; }
    }

    // second best: exclude index mi only
    float w0 = (lane == mi)      ? -CUDART_INF_F : v0;
    float w1 = (lane + 32 == mi) ? -CUDART_INF_F : v1;
    float cv; int ci;
    if (w1 > w0) { cv = w1; ci = lane + 32; } else { cv = w0; ci = lane; }
    float sv = cv; int si = ci;
    #pragma unroll
    for (int off = 16; off; off >>= 1) {
        float ov = __shfl_xor_sync(0xFFFFFFFFu, sv, off);
        int   oi = __shfl_xor_sync(0xFFFFFFFFu, si, off);
        if (ov > sv || (ov == sv && oi < si)) { sv = ov; si = oi; }
    }

    if (lane == 0) {
        // softmax over the two scores (max-subtracted, matches jax.nn.softmax)
        float t  = expf(sv - mv);           // <= 1
        float denom = 1.0f + t;
        float p1 = 1.0f / denom;
        float p2 = t / denom;

        int base = gwarp * 2;
        g_topidx[base]     = mi;
        g_topidx[base + 1] = si;
        g_topp[base]       = p1;
        g_topp[base + 1]   = p2;

        int pos1 = atomicAdd(&g_counts[mi], 1);
        g_elist[(size_t)mi * N_TOK + pos1] = base;
        int pos2 = atomicAdd(&g_counts[si], 1);
        g_elist[(size_t)si * N_TOK + pos2] = base + 1;
    }
}

// ---------------------------------------------------------------------------
// capacity enforcement. One block per expert; only does work on overflow
// (expected never at these shapes: mean load 512, capacity 640).
// Rank ordering: prob desc, token index asc (matches top_k over gates column).
// ---------------------------------------------------------------------------
__global__ void cap_kernel() {
    int e   = blockIdx.x;
    int cnt = g_counts[e];
    if (cnt <= CAPACITY) return;

    const int* lst = g_elist + (size_t)e * N_TOK;
    for (int i = threadIdx.x; i < cnt; i += blockDim.x) {
        int   enc_i = lst[i];
        float pi    = g_topp[enc_i];
        int   ti    = enc_i >> 1;
        int rank = 0;
        for (int j = 0; j < cnt; ++j) {
            int   enc_j = lst[j];
            float pj    = g_topp[enc_j];
            int   tj    = enc_j >> 1;
            rank += (pj > pi) || (pj == pi && tj < ti);
        }
        if (rank >= CAPACITY) g_drop[enc_i] = 1;
    }
}

// ---------------------------------------------------------------------------
// output assembly: [probs (N,2)] [indices-as-float (N,2)] [counts (E)]
// ---------------------------------------------------------------------------
__global__ void out_kernel(float* __restrict__ out) {
    int i = blockIdx.x * blockDim.x + threadIdx.x;
    if (i < 2 * N_TOK) {
        bool d = (g_drop[i] != 0);
        out[i]             = d ? 0.0f : g_topp[i];
        out[2 * N_TOK + i] = d ? 2147483648.0f : (float)g_topidx[i];
    }
    if (i < N_EXP) {
        out[4 * N_TOK + i] = (float)g_counts[i];
    }
}

// ---------------------------------------------------------------------------
extern "C" void kernel_launch(void* const* d_in, const int* in_sizes, int n_in,
                              void* d_out, int out_size) {
    const float* X = (const float*)d_in[0];   // [16384, 4096]
    const float* W = (const float*)d_in[1];   // [64, 4096]
    float* out = (float*)d_out;

    init_kernel<<<(2 * N_TOK + 255) / 256, 256>>>();
    gemm_kernel<<<N_TOK / BM, 256>>>(X, W);
    topk_kernel<<<(N_TOK * 32) / 256, 256>>>();
    cap_kernel<<<N_EXP, 256>>>();
    out_kernel<<<(2 * N_TOK + 255) / 256, 256>>>(out);
}